// round 1
// baseline (speedup 1.0000x reference)
#include <cuda_runtime.h>

// RecurrentFRAdamaxAttention: N*H independent problems, D=M=64 state tiles.
// Pure HBM-streaming kernel: ~1.35 GB total traffic, FLOPs negligible.

#define FR_EPS   1e-6f
#define FR_STEP  0.5f
#define FR_BETA  0.9f
#define FR_DELTA 0.001f

constexpr int Dd = 64;
constexpr int Mm = 64;
constexpr int DM = Dd * Mm;   // 4096
constexpr int NT = 256;       // threads per block

__global__ __launch_bounds__(NT)
void fr_adamax_kernel(
    const float* __restrict__ q_,   // (NH, D)
    const float* __restrict__ k_,   // (NH, D)
    const float* __restrict__ v_,   // (NH, M)
    const float* __restrict__ Sp_,  // Siprev  (NH, D, M)
    const float* __restrict__ Zi_,  // (NH, D)
    const float* __restrict__ Pi_,  // (NH, D, M)
    const float* __restrict__ Mi_,  // (NH, D, M)
    const float* __restrict__ Up_,  // Uiprev  (NH, D, M)
    const float* __restrict__ Sp2_, // Siprev2 (NH, D, M)
    float* __restrict__ oV,         // (NH, M)
    float* __restrict__ oSi,        // (NH, D, M)
    float* __restrict__ oZ,         // (NH, D)
    float* __restrict__ oPi,        // (NH, D, M)
    float* __restrict__ oMi,        // (NH, D, M)
    float* __restrict__ oUi,        // (NH, D, M)
    float* __restrict__ oSp)        // (NH, D, M)  (Siprev passthrough)
{
    const int nh   = blockIdx.x;
    const int t    = threadIdx.x;
    const int lane = t & 31;
    const int warp = t >> 5;
    const int gbase = nh * DM;   // < 2^25, int is fine
    const int dbase = nh * Dd;

    __shared__ float sK[Dd], sVv[Mm], sQ[Dd], sZn[Dd];
    __shared__ float swA[8], swB[8];
    __shared__ float smu, sZ;
    __shared__ float svw[8][16][4];  // per-warp V partials

    // ---- small vectors: feature maps, Zi_new ----
    if (t < Dd) {
        float qv = q_[dbase + t];
        float kv = k_[dbase + t];
        sQ[t] = (qv > 0.f) ? (qv + 1.f) : expf(qv);     // elu(x)+1
        float kf = (kv > 0.f) ? (kv + 1.f) : expf(kv);
        sK[t] = kf;
        float zn = Zi_[dbase + t] + kf;
        sZn[t] = zn;
        oZ[dbase + t] = zn;
        sVv[t] = v_[nh * Mm + t];
    }
    __syncthreads();

    // ---- Phase 1: stream Siprev / Uiprev / Siprev2, norms + Ui + Sp copy ----
    float4 rsp[4];
    float accA = 0.f;  // sum (Ui - Uiprev)^2
    float accB = 0.f;  // sum (Siprev - Siprev2)^2
#pragma unroll
    for (int i = 0; i < 4; i++) {
        const int idx = i * 1024 + t * 4;
        const int d = idx >> 6;
        const int m = idx & 63;
        float4 sp  = *reinterpret_cast<const float4*>(Sp_  + gbase + idx);
        float4 up  = *reinterpret_cast<const float4*>(Up_  + gbase + idx);
        float4 sp2 = *reinterpret_cast<const float4*>(Sp2_ + gbase + idx);
        const float kd = sK[d];
        float4 ui = make_float4(kd * sVv[m], kd * sVv[m + 1],
                                kd * sVv[m + 2], kd * sVv[m + 3]);
        float dx;
        dx = ui.x - up.x;  accA = fmaf(dx, dx, accA);
        dx = ui.y - up.y;  accA = fmaf(dx, dx, accA);
        dx = ui.z - up.z;  accA = fmaf(dx, dx, accA);
        dx = ui.w - up.w;  accA = fmaf(dx, dx, accA);
        dx = sp.x - sp2.x; accB = fmaf(dx, dx, accB);
        dx = sp.y - sp2.y; accB = fmaf(dx, dx, accB);
        dx = sp.z - sp2.z; accB = fmaf(dx, dx, accB);
        dx = sp.w - sp2.w; accB = fmaf(dx, dx, accB);
        *reinterpret_cast<float4*>(oUi + gbase + idx) = ui;
        *reinterpret_cast<float4*>(oSp + gbase + idx) = sp;
        rsp[i] = sp;
    }

    // block reduce both norms
#pragma unroll
    for (int o = 16; o > 0; o >>= 1) {
        accA += __shfl_xor_sync(0xffffffffu, accA, o);
        accB += __shfl_xor_sync(0xffffffffu, accB, o);
    }
    if (lane == 0) { swA[warp] = accA; swB[warp] = accB; }
    __syncthreads();

    if (warp == 0) {
        float a = (lane < 8) ? swA[lane] : 0.f;
        float b = (lane < 8) ? swB[lane] : 0.f;
#pragma unroll
        for (int o = 4; o > 0; o >>= 1) {
            a += __shfl_xor_sync(0xffffffffu, a, o);
            b += __shfl_xor_sync(0xffffffffu, b, o);
        }
        // Z = 1/(Q . Zi_new + eps), computed alongside
        float s = sQ[lane] * sZn[lane] + sQ[lane + 32] * sZn[lane + 32];
#pragma unroll
        for (int o = 16; o > 0; o >>= 1)
            s += __shfl_xor_sync(0xffffffffu, s, o);
        if (lane == 0) {
            float n1 = sqrtf(a);
            float n2 = sqrtf(b);
            float r  = 1.f - sqrtf(FR_STEP * n1 / n2);
            float mu = r * r;
            mu = fminf(fmaxf(mu, 0.f), 1.f - FR_DELTA);
            smu = mu;
            sZ  = 1.f / (s + FR_EPS);
        }
    }
    __syncthreads();

    const float mu = smu;
    const float Zv = sZ;

    // ---- Phase 2: stream Pi / Mi, fuse Pi_new, Mi_new, Si, V partials ----
    float vacc0 = 0.f, vacc1 = 0.f, vacc2 = 0.f, vacc3 = 0.f;
#pragma unroll
    for (int i = 0; i < 4; i++) {
        const int idx = i * 1024 + t * 4;
        const int d = idx >> 6;
        const int m = idx & 63;
        float4 pi = *reinterpret_cast<const float4*>(Pi_ + gbase + idx);
        float4 mi = *reinterpret_cast<const float4*>(Mi_ + gbase + idx);
        const float kd = sK[d];
        float4 ui = make_float4(kd * sVv[m], kd * sVv[m + 1],
                                kd * sVv[m + 2], kd * sVv[m + 3]);
        float4 pn, mn, si;
        pn.x = mu * pi.x - FR_STEP * ui.x;
        pn.y = mu * pi.y - FR_STEP * ui.y;
        pn.z = mu * pi.z - FR_STEP * ui.z;
        pn.w = mu * pi.w - FR_STEP * ui.w;
        mn.x = fmaxf(FR_BETA * mi.x, fabsf(ui.x));
        mn.y = fmaxf(FR_BETA * mi.y, fabsf(ui.y));
        mn.z = fmaxf(FR_BETA * mi.z, fabsf(ui.z));
        mn.w = fmaxf(FR_BETA * mi.w, fabsf(ui.w));
        si.x = rsp[i].x - pn.x * rsqrtf(mn.x + 1e-16f);
        si.y = rsp[i].y - pn.y * rsqrtf(mn.y + 1e-16f);
        si.z = rsp[i].z - pn.z * rsqrtf(mn.z + 1e-16f);
        si.w = rsp[i].w - pn.w * rsqrtf(mn.w + 1e-16f);
        *reinterpret_cast<float4*>(oPi + gbase + idx) = pn;
        *reinterpret_cast<float4*>(oMi + gbase + idx) = mn;
        *reinterpret_cast<float4*>(oSi + gbase + idx) = si;
        const float qd = sQ[d];
        vacc0 = fmaf(qd, si.x, vacc0);
        vacc1 = fmaf(qd, si.y, vacc1);
        vacc2 = fmaf(qd, si.z, vacc2);
        vacc3 = fmaf(qd, si.w, vacc3);
    }

    // ---- V reduction: sum over the 16 threads sharing m-group (t & 15) ----
    vacc0 += __shfl_xor_sync(0xffffffffu, vacc0, 16);
    vacc1 += __shfl_xor_sync(0xffffffffu, vacc1, 16);
    vacc2 += __shfl_xor_sync(0xffffffffu, vacc2, 16);
    vacc3 += __shfl_xor_sync(0xffffffffu, vacc3, 16);
    if (lane < 16) {
        svw[warp][lane][0] = vacc0;
        svw[warp][lane][1] = vacc1;
        svw[warp][lane][2] = vacc2;
        svw[warp][lane][3] = vacc3;
    }
    __syncthreads();
    if (t < 64) {
        const int g = t & 15;     // m group
        const int c = t >> 4;     // column within group
        float s = 0.f;
#pragma unroll
        for (int w = 0; w < 8; w++) s += svw[w][g][c];
        oV[nh * Mm + g * 4 + c] = s * Zv;
    }
}

extern "C" void kernel_launch(void* const* d_in, const int* in_sizes, int n_in,
                              void* d_out, int out_size) {
    const float* q   = (const float*)d_in[0];
    const float* k   = (const float*)d_in[1];
    const float* v   = (const float*)d_in[2];
    const float* Sp  = (const float*)d_in[3];
    const float* Zi  = (const float*)d_in[4];
    const float* Pi  = (const float*)d_in[5];
    const float* Mi  = (const float*)d_in[6];
    const float* Up  = (const float*)d_in[7];
    const float* Sp2 = (const float*)d_in[8];

    const int NHD  = in_sizes[0];        // N*H*D
    const int NHM  = in_sizes[2];        // N*H*M
    const int NHDM = in_sizes[3];        // N*H*D*M
    const int NH   = NHD / Dd;           // grid

    float* out = (float*)d_out;
    float* oV  = out;                    // (NH, M)
    float* oSi = oV  + NHM;              // (NH, D, M)
    float* oZ  = oSi + NHDM;             // (NH, D)
    float* oPi = oZ  + NHD;              // (NH, D, M)
    float* oMi = oPi + NHDM;             // (NH, D, M)
    float* oUi = oMi + NHDM;             // (NH, D, M)
    float* oSp = oUi + NHDM;             // (NH, D, M)

    fr_adamax_kernel<<<NH, NT>>>(q, k, v, Sp, Zi, Pi, Mi, Up, Sp2,
                                 oV, oSi, oZ, oPi, oMi, oUi, oSp);
}